// round 6
// baseline (speedup 1.0000x reference)
#include <cuda_runtime.h>
#include <math.h>

#define B_ 65536

// ---------------- scratch (device globals; no allocations) ----------------
// All activations stored [row][batch] so thread<->batch gives coalesced loads.
__device__ float g_dataT[512u * B_];   // [s][b]           128 MB
__device__ float g_mag  [516u * B_];   // [(f*4+t)][b]     135 MB  (f<129, t<4)
__device__ float g_out1 [512u * B_];   // [(c*4+t)][b]     128 MB  (c<128, t<4)
__device__ float g_out2 [128u * B_];   // [(c*2+t)][b]      32 MB  (c<64,  t<2)
__device__ float g_out3 [ 64u * B_];   // [c][b]            16 MB
__device__ float g_out4 [128u * B_];   // [c][b]            32 MB
__device__ float g_gates[512u * B_];   // [g][b]           128 MB

// ---------------- K0: transpose data[B][512] -> dataT[512][B] ----------------
__global__ void k_transpose(const float* __restrict__ x) {
    __shared__ float tile[32][33];
    int b0 = blockIdx.x * 32, s0 = blockIdx.y * 32;
    int tx = threadIdx.x, ty = threadIdx.y;   // 32 x 8
#pragma unroll
    for (int i = 0; i < 32; i += 8)
        tile[ty + i][tx] = x[(size_t)(b0 + ty + i) * 512 + s0 + tx];
    __syncthreads();
#pragma unroll
    for (int i = 0; i < 32; i += 8)
        g_dataT[(size_t)(s0 + ty + i) * B_ + b0 + tx] = tile[tx][ty + i];
}

// ---------------- K1: STFT conv (stride 128) fused with mag ----------------
// spec[b,f,t] = sum_k w[f,k] * padded[b, 128*t + k], padded = [64 zeros | data | reflect 64]
//   t<3        : s = 128*t - 64 + k      (zero if s < 0)
//   t=3, k<192 : s = 320 + k
//   t=3, k>=192: s = 702 - k             (reflect: padded[576+j] = data[510-j])
// mag[f][t][b] = sqrt(spec_f^2 + spec_{129+f}^2).  129 = 3*43 -> grid.y = 3 tiles of 43.
__global__ __launch_bounds__(256) void k_stft(const float* __restrict__ w) {
    const int t  = blockIdx.z;
    const int f0 = blockIdx.y * 43;
    const int b  = blockIdx.x * 256 + threadIdx.x;
    __shared__ float ws[86][64];              // [n][kk]; n<43 real, n>=43 imag
    float acc[86];
#pragma unroll
    for (int n = 0; n < 86; n++) acc[n] = 0.f;

    for (int k0 = 0; k0 < 256; k0 += 64) {
        __syncthreads();
        for (int idx = threadIdx.x; idx < 86 * 64; idx += 256) {
            int n = idx >> 6, kk = idx & 63;
            int f = (n < 43) ? (f0 + n) : (129 + f0 + (n - 43));
            ws[n][kk] = w[f * 256 + k0 + kk];
        }
        __syncthreads();
        for (int kk = 0; kk < 64; kk += 4) {
            float a0, a1, a2, a3;
            {
                int k = k0 + kk;
#define LOADA(i, dst) { int kc = k + (i); \
        int s = (t < 3) ? (128 * t - 64 + kc) : ((kc < 192) ? (320 + kc) : (702 - kc)); \
        dst = ((unsigned)s < 512u) ? g_dataT[(size_t)s * B_ + b] : 0.f; }
                LOADA(0, a0) LOADA(1, a1) LOADA(2, a2) LOADA(3, a3)
#undef LOADA
            }
#pragma unroll
            for (int n = 0; n < 86; n++) {
                float4 w4 = *reinterpret_cast<const float4*>(&ws[n][kk]);
                acc[n] += w4.x * a0 + w4.y * a1 + w4.z * a2 + w4.w * a3;
            }
        }
    }
#pragma unroll
    for (int n = 0; n < 43; n++) {
        float r = acc[n], im = acc[43 + n];
        g_mag[(size_t)((f0 + n) * 4 + t) * B_ + b] = sqrtf(r * r + im * im);
    }
}

// ---------------- K2: e1 conv (k=3, pad=1, stride=1), 129->128, relu --------
// out1[c][t][b] = relu(b1[c] + sum_{ic,j} w[c][ic][j] * mag[ic][t-1+j][b])
__global__ __launch_bounds__(256) void k_e1(const float* __restrict__ w,
                                            const float* __restrict__ bias) {
    const int t  = blockIdx.z;
    const int c0 = blockIdx.y * 64;
    const int b  = blockIdx.x * 256 + threadIdx.x;
    __shared__ float4 ws[64][43];             // {w_j0, w_j1, w_j2, 0}
    float acc[64];
#pragma unroll
    for (int n = 0; n < 64; n++) acc[n] = bias[c0 + n];

    for (int ic0 = 0; ic0 < 129; ic0 += 43) {
        __syncthreads();
        for (int idx = threadIdx.x; idx < 64 * 43; idx += 256) {
            int n = idx / 43, icl = idx % 43;
            const float* p = &w[((size_t)(c0 + n) * 129 + ic0 + icl) * 3];
            ws[n][icl] = make_float4(p[0], p[1], p[2], 0.f);
        }
        __syncthreads();
        for (int icl = 0; icl < 43; icl++) {
            int base = (ic0 + icl) * 4 + t;   // mag row index for tt = t
            float a0 = (t >= 1) ? g_mag[(size_t)(base - 1) * B_ + b] : 0.f;
            float a1 =            g_mag[(size_t)(base    ) * B_ + b];
            float a2 = (t <  3) ? g_mag[(size_t)(base + 1) * B_ + b] : 0.f;
#pragma unroll
            for (int n = 0; n < 64; n++) {
                float4 w4 = ws[n][icl];
                acc[n] += w4.x * a0 + w4.y * a1 + w4.z * a2;
            }
        }
    }
#pragma unroll
    for (int n = 0; n < 64; n++)
        g_out1[(size_t)((c0 + n) * 4 + t) * B_ + b] = fmaxf(acc[n], 0.f);
}

// ---------------- K3: e2 conv (k=3, pad=1, stride=2), 128->64, relu ---------
// out2[c][tp][b], input indices tt = 2*tp - 1 + j  (tp=0: {-1,0,1}; tp=1: {1,2,3})
__global__ __launch_bounds__(256) void k_e2(const float* __restrict__ w,
                                            const float* __restrict__ bias) {
    const int tp = blockIdx.z;
    const int b  = blockIdx.x * 256 + threadIdx.x;
    __shared__ float4 ws[64][32];
    float acc[64];
#pragma unroll
    for (int n = 0; n < 64; n++) acc[n] = bias[n];

    const int tt0 = 2 * tp - 1;
    for (int ic0 = 0; ic0 < 128; ic0 += 32) {
        __syncthreads();
        for (int idx = threadIdx.x; idx < 64 * 32; idx += 256) {
            int n = idx >> 5, icl = idx & 31;
            const float* p = &w[((size_t)n * 128 + ic0 + icl) * 3];
            ws[n][icl] = make_float4(p[0], p[1], p[2], 0.f);
        }
        __syncthreads();
        for (int icl = 0; icl < 32; icl++) {
            int base = (ic0 + icl) * 4;
            float a0 = (tt0 >= 0) ? g_out1[(size_t)(base + tt0) * B_ + b] : 0.f;
            float a1 = g_out1[(size_t)(base + tt0 + 1) * B_ + b];
            float a2 = g_out1[(size_t)(base + tt0 + 2) * B_ + b];
#pragma unroll
            for (int n = 0; n < 64; n++) {
                float4 w4 = ws[n][icl];
                acc[n] += w4.x * a0 + w4.y * a1 + w4.z * a2;
            }
        }
    }
#pragma unroll
    for (int n = 0; n < 64; n++)
        g_out2[(size_t)(n * 2 + tp) * B_ + b] = fmaxf(acc[n], 0.f);
}

// ---------------- K4: e3 conv (k=3, pad=1, stride=2 over len 2) -> len 1 ----
// out3[c][b] = relu(b3[c] + sum_ic (w[c][ic][1]*out2[ic][0] + w[c][ic][2]*out2[ic][1]))
__global__ __launch_bounds__(256) void k_e3(const float* __restrict__ w,
                                            const float* __restrict__ bias) {
    const int b = blockIdx.x * 256 + threadIdx.x;
    __shared__ float4 ws[64][32];             // pair of ic per float4
    float acc[64];
#pragma unroll
    for (int n = 0; n < 64; n++) acc[n] = bias[n];

    for (int idx = threadIdx.x; idx < 64 * 32; idx += 256) {
        int n = idx >> 5, q = idx & 31;
        const float* p0 = &w[((size_t)n * 64 + 2 * q) * 3];
        const float* p1 = &w[((size_t)n * 64 + 2 * q + 1) * 3];
        ws[n][q] = make_float4(p0[1], p0[2], p1[1], p1[2]);
    }
    __syncthreads();
    for (int q = 0; q < 32; q++) {
        float a0 = g_out2[(size_t)(4 * q + 0) * B_ + b];
        float a1 = g_out2[(size_t)(4 * q + 1) * B_ + b];
        float a2 = g_out2[(size_t)(4 * q + 2) * B_ + b];
        float a3 = g_out2[(size_t)(4 * q + 3) * B_ + b];
#pragma unroll
        for (int n = 0; n < 64; n++) {
            float4 w4 = ws[n][q];
            acc[n] += w4.x * a0 + w4.y * a1 + w4.z * a2 + w4.w * a3;
        }
    }
#pragma unroll
    for (int n = 0; n < 64; n++)
        g_out3[(size_t)n * B_ + b] = fmaxf(acc[n], 0.f);
}

// ---------------- K5: e4 conv (k=3, pad=1 over len 1) -> only j=1 tap -------
__global__ __launch_bounds__(256) void k_e4(const float* __restrict__ w,
                                            const float* __restrict__ bias) {
    const int c0 = blockIdx.y * 64;
    const int b  = blockIdx.x * 256 + threadIdx.x;
    __shared__ float4 ws[64][16];
    float acc[64];
#pragma unroll
    for (int n = 0; n < 64; n++) acc[n] = bias[c0 + n];

    for (int idx = threadIdx.x; idx < 64 * 16; idx += 256) {
        int n = idx >> 4, q = idx & 15;
        const float* p = &w[((size_t)(c0 + n) * 64 + 4 * q) * 3];
        ws[n][q] = make_float4(p[1], p[3 + 1], p[6 + 1], p[9 + 1]);
    }
    __syncthreads();
    for (int q = 0; q < 16; q++) {
        float a0 = g_out3[(size_t)(4 * q + 0) * B_ + b];
        float a1 = g_out3[(size_t)(4 * q + 1) * B_ + b];
        float a2 = g_out3[(size_t)(4 * q + 2) * B_ + b];
        float a3 = g_out3[(size_t)(4 * q + 3) * B_ + b];
#pragma unroll
        for (int n = 0; n < 64; n++) {
            float4 w4 = ws[n][q];
            acc[n] += w4.x * a0 + w4.y * a1 + w4.z * a2 + w4.w * a3;
        }
    }
#pragma unroll
    for (int n = 0; n < 64; n++)
        g_out4[(size_t)(c0 + n) * B_ + b] = fmaxf(acc[n], 0.f);
}

// ---------------- K6: LSTM gates = out4 @ w_ih^T + (b_ih + b_hh) ------------
__global__ __launch_bounds__(256) void k_gates(const float* __restrict__ w_ih,
                                               const float* __restrict__ b_ih,
                                               const float* __restrict__ b_hh) {
    const int g0 = blockIdx.y * 64;
    const int b  = blockIdx.x * 256 + threadIdx.x;
    __shared__ float4 ws[64][32];
    float acc[64];
#pragma unroll
    for (int n = 0; n < 64; n++) acc[n] = b_ih[g0 + n] + b_hh[g0 + n];

    for (int idx = threadIdx.x; idx < 64 * 32; idx += 256) {
        int n = idx >> 5, q = idx & 31;
        ws[n][q] = *reinterpret_cast<const float4*>(&w_ih[(size_t)(g0 + n) * 128 + 4 * q]);
    }
    __syncthreads();
    for (int q = 0; q < 32; q++) {
        float a0 = g_out4[(size_t)(4 * q + 0) * B_ + b];
        float a1 = g_out4[(size_t)(4 * q + 1) * B_ + b];
        float a2 = g_out4[(size_t)(4 * q + 2) * B_ + b];
        float a3 = g_out4[(size_t)(4 * q + 3) * B_ + b];
#pragma unroll
        for (int n = 0; n < 64; n++) {
            float4 w4 = ws[n][q];
            acc[n] += w4.x * a0 + w4.y * a1 + w4.z * a2 + w4.w * a3;
        }
    }
#pragma unroll
    for (int n = 0; n < 64; n++)
        g_gates[(size_t)(g0 + n) * B_ + b] = acc[n];
}

// ---------------- K7: LSTM pointwise (h0=c0=0) + decoder + sigmoid ----------
__device__ __forceinline__ float sigf(float x) { return 1.f / (1.f + expf(-x)); }

__global__ __launch_bounds__(256) void k_head(const float* __restrict__ dec_w,
                                              const float* __restrict__ dec_b,
                                              float* __restrict__ out) {
    const int b = blockIdx.x * 256 + threadIdx.x;
    float d = dec_b[0];
    for (int c = 0; c < 128; c++) {
        float ig = g_gates[(size_t)(      c) * B_ + b];
        float gg = g_gates[(size_t)(256 + c) * B_ + b];
        float og = g_gates[(size_t)(384 + c) * B_ + b];
        float cc = sigf(ig) * tanhf(gg);      // f-gate * c0 == 0
        float h  = sigf(og) * tanhf(cc);
        d += fmaxf(h, 0.f) * dec_w[c];
    }
    out[b] = sigf(d);
}

// ---------------- launch -----------------------------------------------------
extern "C" void kernel_launch(void* const* d_in, const int* in_sizes, int n_in,
                              void* d_out, int out_size) {
    const float* data   = (const float*)d_in[0];
    // d_in[1] = sr (int scalar, 16000 -> context 64, baked into k_stft)
    const float* stft_w = (const float*)d_in[2];
    const float* e1_w   = (const float*)d_in[3];
    const float* e1_b   = (const float*)d_in[4];
    const float* e2_w   = (const float*)d_in[5];
    const float* e2_b   = (const float*)d_in[6];
    const float* e3_w   = (const float*)d_in[7];
    const float* e3_b   = (const float*)d_in[8];
    const float* e4_w   = (const float*)d_in[9];
    const float* e4_b   = (const float*)d_in[10];
    const float* w_ih   = (const float*)d_in[11];
    // d_in[12] = w_hh (dead: h0 == 0)
    const float* b_ih   = (const float*)d_in[13];
    const float* b_hh   = (const float*)d_in[14];
    const float* dec_w  = (const float*)d_in[15];
    const float* dec_b  = (const float*)d_in[16];
    float* out = (float*)d_out;

    dim3 blk(256);
    k_transpose<<<dim3(B_ / 32, 16), dim3(32, 8)>>>(data);
    k_stft     <<<dim3(B_ / 256, 3, 4), blk>>>(stft_w);
    k_e1       <<<dim3(B_ / 256, 2, 4), blk>>>(e1_w, e1_b);
    k_e2       <<<dim3(B_ / 256, 1, 2), blk>>>(e2_w, e2_b);
    k_e3       <<<dim3(B_ / 256),       blk>>>(e3_w, e3_b);
    k_e4       <<<dim3(B_ / 256, 2),    blk>>>(e4_w, e4_b);
    k_gates    <<<dim3(B_ / 256, 8),    blk>>>(w_ih, b_ih, b_hh);
    k_head     <<<dim3(B_ / 256),       blk>>>(dec_w, dec_b, out);
}

// round 10
// speedup vs baseline: 1.5121x; 1.5121x over previous
#include <cuda_runtime.h>
#include <math.h>

#define B_ 65536
typedef unsigned long long u64;
typedef ulonglong2 u64x2;

// ---------------- f32x2 helpers (FFMA2 only reachable via PTX) --------------
__device__ __forceinline__ u64 fma2(u64 w, u64 a, u64 c) {
    u64 d; asm("fma.rn.f32x2 %0, %1, %2, %3;" : "=l"(d) : "l"(w), "l"(a), "l"(c));
    return d;
}
__device__ __forceinline__ u64 pack2(float x, float y) {
    u64 d; asm("mov.b64 %0, {%1, %2};" : "=l"(d)
               : "r"(__float_as_uint(x)), "r"(__float_as_uint(y)));
    return d;
}
__device__ __forceinline__ float lo32(u64 v) { return __uint_as_float((unsigned)v); }
__device__ __forceinline__ float hi32(u64 v) { return __uint_as_float((unsigned)(v >> 32)); }
__device__ __forceinline__ u64 ld2(const float* p) { return *reinterpret_cast<const u64*>(p); }
__device__ __forceinline__ void st2(float* p, u64 v) { *reinterpret_cast<u64*>(p) = v; }
__device__ __forceinline__ u64 duplo(u64 v) { float x = lo32(v); return pack2(x, x); }
__device__ __forceinline__ u64 duphi(u64 v) { float x = hi32(v); return pack2(x, x); }

// ---------------- scratch (device globals; no allocations) ------------------
__device__ float g_dataT[512u * B_];   // [s][b]
__device__ float g_mag  [516u * B_];   // [(f*4+t)][b]   f<129, t<4
__device__ float g_out1 [512u * B_];   // [(c*4+t)][b]   c<128
__device__ float g_out2 [128u * B_];   // [(c*2+t)][b]   c<64
__device__ float g_out3 [ 64u * B_];   // [c][b]
__device__ float g_out4 [128u * B_];   // [c][b]
__device__ float g_gates[512u * B_];   // [g][b]

// ---------------- K0: transpose data[B][512] -> dataT[512][B] ---------------
__global__ void k_transpose(const float* __restrict__ x) {
    __shared__ float tile[32][33];
    int b0 = blockIdx.x * 32, s0 = blockIdx.y * 32;
    int tx = threadIdx.x, ty = threadIdx.y;   // 32 x 8
#pragma unroll
    for (int i = 0; i < 32; i += 8)
        tile[ty + i][tx] = x[(size_t)(b0 + ty + i) * 512 + s0 + tx];
    __syncthreads();
#pragma unroll
    for (int i = 0; i < 32; i += 8)
        g_dataT[(size_t)(s0 + ty + i) * B_ + b0 + tx] = tile[tx][ty + i];
}

// ---------------- K1: STFT (stride 128) fused with mag ----------------------
// f32x2 lanes = (Real_f, Imag_f) of one frequency; 2 batches per thread.
//   t<3        : s = 128*t - 64 + k     (zero if s<0)
//   t=3, k<192 : s = 320 + k
//   t=3, k>=192: s = 702 - k            (reflect)
#define FT 20
__global__ __launch_bounds__(256, 2) void k_stft(const float* __restrict__ w) {
    const int t  = blockIdx.z;
    const int f0 = blockIdx.y * FT;
    const int b  = (blockIdx.x * 256 + threadIdx.x) * 2;
    __shared__ float ws[64][2 * FT];          // [kk][2*m+isI]
    u64 acc0[FT], acc1[FT];
#pragma unroll
    for (int m = 0; m < FT; m++) { acc0[m] = 0ull; acc1[m] = 0ull; }

    for (int k0 = 0; k0 < 256; k0 += 64) {
        __syncthreads();
        for (int idx = threadIdx.x; idx < 64 * 2 * FT; idx += 256) {
            int kk = idx / (2 * FT), r = idx % (2 * FT);
            int m = r >> 1, isI = r & 1, f = f0 + m;
            ws[kk][r] = (f < 129) ? w[(f + 129 * isI) * 256 + k0 + kk] : 0.f;
        }
        __syncthreads();
#pragma unroll 4
        for (int kk = 0; kk < 64; kk++) {
            int kc = k0 + kk;
            int s = (t < 3) ? (128 * t - 64 + kc)
                            : ((kc < 192) ? (320 + kc) : (702 - kc));
            u64 av = ((unsigned)s < 512u) ? ld2(&g_dataT[(size_t)s * B_ + b]) : 0ull;
            u64 A0 = duplo(av), A1 = duphi(av);
#pragma unroll
            for (int q = 0; q < FT / 2; q++) {
                u64x2 W = *reinterpret_cast<const u64x2*>(&ws[kk][4 * q]);
                acc0[2 * q]     = fma2(W.x, A0, acc0[2 * q]);
                acc1[2 * q]     = fma2(W.x, A1, acc1[2 * q]);
                acc0[2 * q + 1] = fma2(W.y, A0, acc0[2 * q + 1]);
                acc1[2 * q + 1] = fma2(W.y, A1, acc1[2 * q + 1]);
            }
        }
    }
#pragma unroll
    for (int m = 0; m < FT; m++) {
        int f = f0 + m;
        if (f < 129) {
            float r0 = lo32(acc0[m]), i0 = hi32(acc0[m]);
            float r1 = lo32(acc1[m]), i1 = hi32(acc1[m]);
            st2(&g_mag[(size_t)(f * 4 + t) * B_ + b],
                pack2(sqrtf(r0 * r0 + i0 * i0), sqrtf(r1 * r1 + i1 * i1)));
        }
    }
}

// ---------------- K2: e1 conv (k=3, pad=1), 129->128, relu ------------------
// f32x2 lanes = 2 output channels; 2 batches/thread; 32-channel tile.
__global__ __launch_bounds__(256, 2) void k_e1(const float* __restrict__ w,
                                               const float* __restrict__ bias) {
    const int t  = blockIdx.z;
    const int c0 = blockIdx.y * 32;
    const int b  = (blockIdx.x * 256 + threadIdx.x) * 2;
    __shared__ float ws[43][3][32];
    u64 acc0[16], acc1[16];
#pragma unroll
    for (int m = 0; m < 16; m++) {
        u64 bv = pack2(bias[c0 + 2 * m], bias[c0 + 2 * m + 1]);
        acc0[m] = bv; acc1[m] = bv;
    }
    for (int ic0 = 0; ic0 < 129; ic0 += 43) {
        __syncthreads();
        for (int idx = threadIdx.x; idx < 43 * 3 * 32; idx += 256) {
            int icl = idx / 96, r = idx % 96, j = r >> 5, cc = r & 31;
            ws[icl][j][cc] = w[((size_t)(c0 + cc) * 129 + ic0 + icl) * 3 + j];
        }
        __syncthreads();
        for (int icl = 0; icl < 43; icl++) {
            int base = (ic0 + icl) * 4 + t;
            u64 v0 = (t >= 1) ? ld2(&g_mag[(size_t)(base - 1) * B_ + b]) : 0ull;
            u64 v1 =            ld2(&g_mag[(size_t)(base    ) * B_ + b]);
            u64 v2 = (t <  3) ? ld2(&g_mag[(size_t)(base + 1) * B_ + b]) : 0ull;
            u64 A00 = duplo(v0), A01 = duphi(v0);
            u64 A10 = duplo(v1), A11 = duphi(v1);
            u64 A20 = duplo(v2), A21 = duphi(v2);
#pragma unroll
            for (int q = 0; q < 8; q++) {
                u64x2 W0 = *(const u64x2*)&ws[icl][0][4 * q];
                u64x2 W1 = *(const u64x2*)&ws[icl][1][4 * q];
                u64x2 W2 = *(const u64x2*)&ws[icl][2][4 * q];
                acc0[2*q]   = fma2(W0.x, A00, acc0[2*q]);
                acc0[2*q]   = fma2(W1.x, A10, acc0[2*q]);
                acc0[2*q]   = fma2(W2.x, A20, acc0[2*q]);
                acc0[2*q+1] = fma2(W0.y, A00, acc0[2*q+1]);
                acc0[2*q+1] = fma2(W1.y, A10, acc0[2*q+1]);
                acc0[2*q+1] = fma2(W2.y, A20, acc0[2*q+1]);
                acc1[2*q]   = fma2(W0.x, A01, acc1[2*q]);
                acc1[2*q]   = fma2(W1.x, A11, acc1[2*q]);
                acc1[2*q]   = fma2(W2.x, A21, acc1[2*q]);
                acc1[2*q+1] = fma2(W0.y, A01, acc1[2*q+1]);
                acc1[2*q+1] = fma2(W1.y, A11, acc1[2*q+1]);
                acc1[2*q+1] = fma2(W2.y, A21, acc1[2*q+1]);
            }
        }
    }
#pragma unroll
    for (int m = 0; m < 16; m++) {
        int c = c0 + 2 * m;
        st2(&g_out1[(size_t)(c * 4 + t) * B_ + b],
            pack2(fmaxf(lo32(acc0[m]), 0.f), fmaxf(lo32(acc1[m]), 0.f)));
        st2(&g_out1[(size_t)((c + 1) * 4 + t) * B_ + b],
            pack2(fmaxf(hi32(acc0[m]), 0.f), fmaxf(hi32(acc1[m]), 0.f)));
    }
}

// ---------------- K3: e2 conv (k=3, pad=1, stride=2), 128->64, relu ---------
__global__ __launch_bounds__(256, 2) void k_e2(const float* __restrict__ w,
                                               const float* __restrict__ bias) {
    const int tp = blockIdx.z;
    const int c0 = blockIdx.y * 32;
    const int b  = (blockIdx.x * 256 + threadIdx.x) * 2;
    __shared__ float ws[32][3][32];
    u64 acc0[16], acc1[16];
#pragma unroll
    for (int m = 0; m < 16; m++) {
        u64 bv = pack2(bias[c0 + 2 * m], bias[c0 + 2 * m + 1]);
        acc0[m] = bv; acc1[m] = bv;
    }
    const int tt0 = 2 * tp - 1;
    for (int ic0 = 0; ic0 < 128; ic0 += 32) {
        __syncthreads();
        for (int idx = threadIdx.x; idx < 32 * 3 * 32; idx += 256) {
            int icl = idx / 96, r = idx % 96, j = r >> 5, cc = r & 31;
            ws[icl][j][cc] = w[((size_t)(c0 + cc) * 128 + ic0 + icl) * 3 + j];
        }
        __syncthreads();
        for (int icl = 0; icl < 32; icl++) {
            int base = (ic0 + icl) * 4;
            u64 v0 = (tt0 >= 0) ? ld2(&g_out1[(size_t)(base + tt0) * B_ + b]) : 0ull;
            u64 v1 = ld2(&g_out1[(size_t)(base + tt0 + 1) * B_ + b]);
            u64 v2 = ld2(&g_out1[(size_t)(base + tt0 + 2) * B_ + b]);
            u64 A00 = duplo(v0), A01 = duphi(v0);
            u64 A10 = duplo(v1), A11 = duphi(v1);
            u64 A20 = duplo(v2), A21 = duphi(v2);
#pragma unroll
            for (int q = 0; q < 8; q++) {
                u64x2 W0 = *(const u64x2*)&ws[icl][0][4 * q];
                u64x2 W1 = *(const u64x2*)&ws[icl][1][4 * q];
                u64x2 W2 = *(const u64x2*)&ws[icl][2][4 * q];
                acc0[2*q]   = fma2(W0.x, A00, acc0[2*q]);
                acc0[2*q]   = fma2(W1.x, A10, acc0[2*q]);
                acc0[2*q]   = fma2(W2.x, A20, acc0[2*q]);
                acc0[2*q+1] = fma2(W0.y, A00, acc0[2*q+1]);
                acc0[2*q+1] = fma2(W1.y, A10, acc0[2*q+1]);
                acc0[2*q+1] = fma2(W2.y, A20, acc0[2*q+1]);
                acc1[2*q]   = fma2(W0.x, A01, acc1[2*q]);
                acc1[2*q]   = fma2(W1.x, A11, acc1[2*q]);
                acc1[2*q]   = fma2(W2.x, A21, acc1[2*q]);
                acc1[2*q+1] = fma2(W0.y, A01, acc1[2*q+1]);
                acc1[2*q+1] = fma2(W1.y, A11, acc1[2*q+1]);
                acc1[2*q+1] = fma2(W2.y, A21, acc1[2*q+1]);
            }
        }
    }
#pragma unroll
    for (int m = 0; m < 16; m++) {
        int c = c0 + 2 * m;
        st2(&g_out2[(size_t)(c * 2 + tp) * B_ + b],
            pack2(fmaxf(lo32(acc0[m]), 0.f), fmaxf(lo32(acc1[m]), 0.f)));
        st2(&g_out2[(size_t)((c + 1) * 2 + tp) * B_ + b],
            pack2(fmaxf(hi32(acc0[m]), 0.f), fmaxf(hi32(acc1[m]), 0.f)));
    }
}

// ---------------- generic GEMM core (K rows of src -> 32-channel tile) ------
// ws must be staged as ws[k][cc] = weight for output channel (c0+cc), k-term.
template <int K>
__device__ __forceinline__ void gemm_tail(const float ws[][32], const float* src,
                                          int b, u64 acc0[16], u64 acc1[16]) {
    for (int k = 0; k < K; k++) {
        u64 av = ld2(&src[(size_t)k * B_ + b]);
        u64 A0 = duplo(av), A1 = duphi(av);
#pragma unroll
        for (int q = 0; q < 8; q++) {
            u64x2 W = *(const u64x2*)&ws[k][4 * q];
            acc0[2*q]   = fma2(W.x, A0, acc0[2*q]);
            acc0[2*q+1] = fma2(W.y, A0, acc0[2*q+1]);
            acc1[2*q]   = fma2(W.x, A1, acc1[2*q]);
            acc1[2*q+1] = fma2(W.y, A1, acc1[2*q+1]);
        }
    }
}

// ---------------- K4: e3 (effective GEMM K=128 over g_out2), relu -----------
__global__ __launch_bounds__(256, 2) void k_e3(const float* __restrict__ w,
                                               const float* __restrict__ bias) {
    const int c0 = blockIdx.y * 32;
    const int b  = (blockIdx.x * 256 + threadIdx.x) * 2;
    __shared__ float ws[128][32];
    for (int idx = threadIdx.x; idx < 128 * 32; idx += 256) {
        int k = idx >> 5, cc = idx & 31, ic = k >> 1, tp = k & 1;
        ws[k][cc] = w[((size_t)(c0 + cc) * 64 + ic) * 3 + 1 + tp];
    }
    u64 acc0[16], acc1[16];
#pragma unroll
    for (int m = 0; m < 16; m++) {
        u64 bv = pack2(bias[c0 + 2 * m], bias[c0 + 2 * m + 1]);
        acc0[m] = bv; acc1[m] = bv;
    }
    __syncthreads();
    gemm_tail<128>(ws, g_out2, b, acc0, acc1);
#pragma unroll
    for (int m = 0; m < 16; m++) {
        int c = c0 + 2 * m;
        st2(&g_out3[(size_t)c * B_ + b],
            pack2(fmaxf(lo32(acc0[m]), 0.f), fmaxf(lo32(acc1[m]), 0.f)));
        st2(&g_out3[(size_t)(c + 1) * B_ + b],
            pack2(fmaxf(hi32(acc0[m]), 0.f), fmaxf(hi32(acc1[m]), 0.f)));
    }
}

// ---------------- K5: e4 (GEMM K=64 over g_out3, only tap j=1), relu --------
__global__ __launch_bounds__(256, 2) void k_e4(const float* __restrict__ w,
                                               const float* __restrict__ bias) {
    const int c0 = blockIdx.y * 32;
    const int b  = (blockIdx.x * 256 + threadIdx.x) * 2;
    __shared__ float ws[64][32];
    for (int idx = threadIdx.x; idx < 64 * 32; idx += 256) {
        int k = idx >> 5, cc = idx & 31;
        ws[k][cc] = w[((size_t)(c0 + cc) * 64 + k) * 3 + 1];
    }
    u64 acc0[16], acc1[16];
#pragma unroll
    for (int m = 0; m < 16; m++) {
        u64 bv = pack2(bias[c0 + 2 * m], bias[c0 + 2 * m + 1]);
        acc0[m] = bv; acc1[m] = bv;
    }
    __syncthreads();
    gemm_tail<64>(ws, g_out3, b, acc0, acc1);
#pragma unroll
    for (int m = 0; m < 16; m++) {
        int c = c0 + 2 * m;
        st2(&g_out4[(size_t)c * B_ + b],
            pack2(fmaxf(lo32(acc0[m]), 0.f), fmaxf(lo32(acc1[m]), 0.f)));
        st2(&g_out4[(size_t)(c + 1) * B_ + b],
            pack2(fmaxf(hi32(acc0[m]), 0.f), fmaxf(hi32(acc1[m]), 0.f)));
    }
}

// ---------------- K6: LSTM gates (GEMM K=128 over g_out4) -------------------
__global__ __launch_bounds__(256, 2) void k_gates(const float* __restrict__ w_ih,
                                                  const float* __restrict__ b_ih,
                                                  const float* __restrict__ b_hh) {
    const int g0 = blockIdx.y * 32;
    const int b  = (blockIdx.x * 256 + threadIdx.x) * 2;
    __shared__ float ws[128][32];
    for (int idx = threadIdx.x; idx < 128 * 32; idx += 256) {
        int k = idx >> 5, cc = idx & 31;
        ws[k][cc] = w_ih[(size_t)(g0 + cc) * 128 + k];
    }
    u64 acc0[16], acc1[16];
#pragma unroll
    for (int m = 0; m < 16; m++) {
        u64 bv = pack2(b_ih[g0 + 2 * m] + b_hh[g0 + 2 * m],
                       b_ih[g0 + 2 * m + 1] + b_hh[g0 + 2 * m + 1]);
        acc0[m] = bv; acc1[m] = bv;
    }
    __syncthreads();
    gemm_tail<128>(ws, g_out4, b, acc0, acc1);
#pragma unroll
    for (int m = 0; m < 16; m++) {
        int g = g0 + 2 * m;
        st2(&g_gates[(size_t)g * B_ + b], pack2(lo32(acc0[m]), lo32(acc1[m])));
        st2(&g_gates[(size_t)(g + 1) * B_ + b], pack2(hi32(acc0[m]), hi32(acc1[m])));
    }
}

// ---------------- K7: LSTM pointwise (h0=c0=0) + decoder + sigmoid ----------
__device__ __forceinline__ float sigf(float x) { return 1.f / (1.f + expf(-x)); }

__global__ __launch_bounds__(256) void k_head(const float* __restrict__ dec_w,
                                              const float* __restrict__ dec_b,
                                              float* __restrict__ out) {
    const int b = (blockIdx.x * 256 + threadIdx.x) * 2;
    __shared__ float wd[128];
    if (threadIdx.x < 128) wd[threadIdx.x] = dec_w[threadIdx.x];
    __syncthreads();
    float d0 = dec_b[0], d1 = d0;
    for (int c = 0; c < 128; c++) {
        u64 ig = ld2(&g_gates[(size_t)(      c) * B_ + b]);
        u64 gg = ld2(&g_gates[(size_t)(256 + c) * B_ + b]);
        u64 og = ld2(&g_gates[(size_t)(384 + c) * B_ + b]);
        float wc = wd[c];
        float cA = sigf(lo32(ig)) * tanhf(lo32(gg));
        float hA = sigf(lo32(og)) * tanhf(cA);
        d0 += fmaxf(hA, 0.f) * wc;
        float cB = sigf(hi32(ig)) * tanhf(hi32(gg));
        float hB = sigf(hi32(og)) * tanhf(cB);
        d1 += fmaxf(hB, 0.f) * wc;
    }
    st2(&out[b], pack2(sigf(d0), sigf(d1)));
}

// ---------------- launch -----------------------------------------------------
extern "C" void kernel_launch(void* const* d_in, const int* in_sizes, int n_in,
                              void* d_out, int out_size) {
    const float* data   = (const float*)d_in[0];
    // d_in[1] = sr (16000 -> context 64, baked in)
    const float* stft_w = (const float*)d_in[2];
    const float* e1_w   = (const float*)d_in[3];
    const float* e1_b   = (const float*)d_in[4];
    const float* e2_w   = (const float*)d_in[5];
    const float* e2_b   = (const float*)d_in[6];
    const float* e3_w   = (const float*)d_in[7];
    const float* e3_b   = (const float*)d_in[8];
    const float* e4_w   = (const float*)d_in[9];
    const float* e4_b   = (const float*)d_in[10];
    const float* w_ih   = (const float*)d_in[11];
    // d_in[12] = w_hh (dead: h0 == 0)
    const float* b_ih   = (const float*)d_in[13];
    const float* b_hh   = (const float*)d_in[14];
    const float* dec_w  = (const float*)d_in[15];
    const float* dec_b  = (const float*)d_in[16];
    float* out = (float*)d_out;

    dim3 blk(256);
    k_transpose<<<dim3(B_ / 32, 16), dim3(32, 8)>>>(data);
    k_stft     <<<dim3(B_ / 512, 7, 4), blk>>>(stft_w);
    k_e1       <<<dim3(B_ / 512, 4, 4), blk>>>(e1_w, e1_b);
    k_e2       <<<dim3(B_ / 512, 2, 2), blk>>>(e2_w, e2_b);
    k_e3       <<<dim3(B_ / 512, 2),    blk>>>(e3_w, e3_b);
    k_e4       <<<dim3(B_ / 512, 4),    blk>>>(e4_w, e4_b);
    k_gates    <<<dim3(B_ / 512, 16),   blk>>>(w_ih, b_ih, b_hh);
    k_head     <<<dim3(B_ / 512),       blk>>>(dec_w, dec_b, out);
}

// round 11
// speedup vs baseline: 1.8473x; 1.2217x over previous
#include <cuda_runtime.h>
#include <math.h>

#define B_ 65536
typedef unsigned long long u64;
typedef ulonglong2 u64x2;

// ---------------- f32x2 helpers (FFMA2 only reachable via PTX) --------------
__device__ __forceinline__ u64 fma2(u64 w, u64 a, u64 c) {
    u64 d; asm("fma.rn.f32x2 %0, %1, %2, %3;" : "=l"(d) : "l"(w), "l"(a), "l"(c));
    return d;
}
__device__ __forceinline__ u64 pack2(float x, float y) {
    u64 d; asm("mov.b64 %0, {%1, %2};" : "=l"(d)
               : "r"(__float_as_uint(x)), "r"(__float_as_uint(y)));
    return d;
}
__device__ __forceinline__ float lo32(u64 v) { return __uint_as_float((unsigned)v); }
__device__ __forceinline__ float hi32(u64 v) { return __uint_as_float((unsigned)(v >> 32)); }
__device__ __forceinline__ u64 ld2(const float* p) { return *reinterpret_cast<const u64*>(p); }
__device__ __forceinline__ void st2(float* p, u64 v) { *reinterpret_cast<u64*>(p) = v; }

__device__ __forceinline__ float4 relu4(float4 v) {
    return make_float4(fmaxf(v.x, 0.f), fmaxf(v.y, 0.f),
                       fmaxf(v.z, 0.f), fmaxf(v.w, 0.f));
}

// ---------------- scratch (device globals; no allocations) ------------------
__device__ float g_dataT[512u * B_];   // [s][b]
__device__ float g_mag  [516u * B_];   // [(f*4+t)][b]   f<129, t<4
__device__ float g_out1 [512u * B_];   // [(c*4+t)][b]   c<128
__device__ float g_out2 [128u * B_];   // [(c*2+t)][b]   c<64
__device__ float g_out3 [ 64u * B_];   // [c][b]
__device__ float g_out4 [128u * B_];   // [c][b]
__device__ float g_gates[512u * B_];   // [g][b]

// ---- core tap: 16 floats of weights (warp-uniform, SMEM) x 4 batches -------
// acc[m][p]: f32x2 = output channels (c0+2m, c0+2m+1), batch b+p.
__device__ __forceinline__ void tap16(const float* __restrict__ wrow,
                                      float4 v, u64 (&acc)[8][4]) {
    u64 A0 = pack2(v.x, v.x), A1 = pack2(v.y, v.y),
        A2 = pack2(v.z, v.z), A3 = pack2(v.w, v.w);
#pragma unroll
    for (int q = 0; q < 4; q++) {
        u64x2 W = *reinterpret_cast<const u64x2*>(wrow + 4 * q);
        acc[2*q  ][0] = fma2(W.x, A0, acc[2*q  ][0]);
        acc[2*q  ][1] = fma2(W.x, A1, acc[2*q  ][1]);
        acc[2*q  ][2] = fma2(W.x, A2, acc[2*q  ][2]);
        acc[2*q  ][3] = fma2(W.x, A3, acc[2*q  ][3]);
        acc[2*q+1][0] = fma2(W.y, A0, acc[2*q+1][0]);
        acc[2*q+1][1] = fma2(W.y, A1, acc[2*q+1][1]);
        acc[2*q+1][2] = fma2(W.y, A2, acc[2*q+1][2]);
        acc[2*q+1][3] = fma2(W.y, A3, acc[2*q+1][3]);
    }
}
__device__ __forceinline__ float4 lo4(const u64 a[4]) {
    return make_float4(lo32(a[0]), lo32(a[1]), lo32(a[2]), lo32(a[3]));
}
__device__ __forceinline__ float4 hi4(const u64 a[4]) {
    return make_float4(hi32(a[0]), hi32(a[1]), hi32(a[2]), hi32(a[3]));
}
__device__ __forceinline__ void init_bias(u64 (&acc)[8][4],
                                          const float* bias, int c0) {
#pragma unroll
    for (int m = 0; m < 8; m++) {
        u64 bv = pack2(bias[c0 + 2 * m], bias[c0 + 2 * m + 1]);
#pragma unroll
        for (int p = 0; p < 4; p++) acc[m][p] = bv;
    }
}

// ---------------- K0: transpose data[B][512] -> dataT[512][B] ---------------
__global__ void k_transpose(const float* __restrict__ x) {
    __shared__ float tile[32][33];
    int b0 = blockIdx.x * 32, s0 = blockIdx.y * 32;
    int tx = threadIdx.x, ty = threadIdx.y;   // 32 x 8
#pragma unroll
    for (int i = 0; i < 32; i += 8)
        tile[ty + i][tx] = x[(size_t)(b0 + ty + i) * 512 + s0 + tx];
    __syncthreads();
#pragma unroll
    for (int i = 0; i < 32; i += 8)
        g_dataT[(size_t)(s0 + ty + i) * B_ + b0 + tx] = tile[tx][ty + i];
}

// ---------------- K1: STFT (stride 128) fused with mag ----------------------
// f32x2 lanes = (Real_f, Imag_f); 8 freqs/tile, 4 batches/thread.
//   t<3        : s = 128*t - 64 + k   (zero if s<0)
//   t=3, k<192 : s = 320 + k
//   t=3, k>=192: s = 702 - k          (reflect)
__global__ __launch_bounds__(256, 2) void k_stft(const float* __restrict__ w) {
    const int t  = blockIdx.z;
    const int f0 = blockIdx.y * 8;
    const int b  = (blockIdx.x * 256 + threadIdx.x) * 4;
    __shared__ float ws[256][16];             // [kk][2*m + isImag]
    for (int idx = threadIdx.x; idx < 256 * 16; idx += 256) {
        int kk = idx >> 4, r = idx & 15, m = r >> 1, isI = r & 1;
        int f = f0 + m;
        ws[kk][r] = (f < 129) ? w[(f + 129 * isI) * 256 + kk] : 0.f;
    }
    u64 acc[8][4];
#pragma unroll
    for (int m = 0; m < 8; m++)
#pragma unroll
        for (int p = 0; p < 4; p++) acc[m][p] = 0ull;
    __syncthreads();

#pragma unroll 4
    for (int kk = 0; kk < 256; kk++) {
        int s = (t < 3) ? (128 * t - 64 + kk)
                        : ((kk < 192) ? (320 + kk) : (702 - kk));
        float4 v = ((unsigned)s < 512u)
                     ? *reinterpret_cast<const float4*>(&g_dataT[(size_t)s * B_ + b])
                     : make_float4(0.f, 0.f, 0.f, 0.f);
        tap16(ws[kk], v, acc);
    }
#pragma unroll
    for (int m = 0; m < 8; m++) {
        int f = f0 + m;
        if (f < 129) {
            float4 mg;
            mg.x = sqrtf(lo32(acc[m][0]) * lo32(acc[m][0]) + hi32(acc[m][0]) * hi32(acc[m][0]));
            mg.y = sqrtf(lo32(acc[m][1]) * lo32(acc[m][1]) + hi32(acc[m][1]) * hi32(acc[m][1]));
            mg.z = sqrtf(lo32(acc[m][2]) * lo32(acc[m][2]) + hi32(acc[m][2]) * hi32(acc[m][2]));
            mg.w = sqrtf(lo32(acc[m][3]) * lo32(acc[m][3]) + hi32(acc[m][3]) * hi32(acc[m][3]));
            *reinterpret_cast<float4*>(&g_mag[(size_t)(f * 4 + t) * B_ + b]) = mg;
        }
    }
}

// ---------------- K2: e1 conv (k=3, pad=1), 129->128, relu ------------------
__global__ __launch_bounds__(256, 2) void k_e1(const float* __restrict__ w,
                                               const float* __restrict__ bias) {
    const int t  = blockIdx.z;
    const int c0 = blockIdx.y * 16;
    const int b  = (blockIdx.x * 256 + threadIdx.x) * 4;
    __shared__ float ws[129][3][16];          // 24.75 KB
    for (int idx = threadIdx.x; idx < 129 * 3 * 16; idx += 256) {
        int ic = idx / 48, r = idx % 48, j = r >> 4, cc = r & 15;
        ws[ic][j][cc] = w[((size_t)(c0 + cc) * 129 + ic) * 3 + j];
    }
    u64 acc[8][4];
    init_bias(acc, bias, c0);
    __syncthreads();

    const float4 z4 = make_float4(0.f, 0.f, 0.f, 0.f);
    for (int ic = 0; ic < 129; ic++) {
        int base = ic * 4 + t;
        float4 v0 = (t >= 1) ? *reinterpret_cast<const float4*>(&g_mag[(size_t)(base - 1) * B_ + b]) : z4;
        float4 v1 =            *reinterpret_cast<const float4*>(&g_mag[(size_t)(base    ) * B_ + b]);
        float4 v2 = (t <  3) ? *reinterpret_cast<const float4*>(&g_mag[(size_t)(base + 1) * B_ + b]) : z4;
        tap16(ws[ic][0], v0, acc);
        tap16(ws[ic][1], v1, acc);
        tap16(ws[ic][2], v2, acc);
    }
#pragma unroll
    for (int m = 0; m < 8; m++) {
        int c = c0 + 2 * m;
        *reinterpret_cast<float4*>(&g_out1[(size_t)(c * 4 + t) * B_ + b])       = relu4(lo4(acc[m]));
        *reinterpret_cast<float4*>(&g_out1[(size_t)((c + 1) * 4 + t) * B_ + b]) = relu4(hi4(acc[m]));
    }
}

// ---------------- K3: e2 conv (k=3, pad=1, stride=2), 128->64, relu ---------
__global__ __launch_bounds__(256, 2) void k_e2(const float* __restrict__ w,
                                               const float* __restrict__ bias) {
    const int tp = blockIdx.z;
    const int c0 = blockIdx.y * 16;
    const int b  = (blockIdx.x * 256 + threadIdx.x) * 4;
    __shared__ float ws[128][3][16];          // 24 KB
    for (int idx = threadIdx.x; idx < 128 * 3 * 16; idx += 256) {
        int ic = idx / 48, r = idx % 48, j = r >> 4, cc = r & 15;
        ws[ic][j][cc] = w[((size_t)(c0 + cc) * 128 + ic) * 3 + j];
    }
    u64 acc[8][4];
    init_bias(acc, bias, c0);
    __syncthreads();

    const int tt0 = 2 * tp - 1;
    const float4 z4 = make_float4(0.f, 0.f, 0.f, 0.f);
    for (int ic = 0; ic < 128; ic++) {
        int base = ic * 4;
        float4 v0 = (tt0 >= 0) ? *reinterpret_cast<const float4*>(&g_out1[(size_t)(base + tt0) * B_ + b]) : z4;
        float4 v1 = *reinterpret_cast<const float4*>(&g_out1[(size_t)(base + tt0 + 1) * B_ + b]);
        float4 v2 = *reinterpret_cast<const float4*>(&g_out1[(size_t)(base + tt0 + 2) * B_ + b]);
        tap16(ws[ic][0], v0, acc);
        tap16(ws[ic][1], v1, acc);
        tap16(ws[ic][2], v2, acc);
    }
#pragma unroll
    for (int m = 0; m < 8; m++) {
        int c = c0 + 2 * m;
        *reinterpret_cast<float4*>(&g_out2[(size_t)(c * 2 + tp) * B_ + b])       = relu4(lo4(acc[m]));
        *reinterpret_cast<float4*>(&g_out2[(size_t)((c + 1) * 2 + tp) * B_ + b]) = relu4(hi4(acc[m]));
    }
}

// ---------------- generic GEMM core: K rows of src -> 16-channel tile -------
template <int K>
__device__ __forceinline__ void gemm_core(const float ws[][16], const float* src,
                                          int b, u64 (&acc)[8][4]) {
#pragma unroll 4
    for (int k = 0; k < K; k++) {
        float4 v = *reinterpret_cast<const float4*>(&src[(size_t)k * B_ + b]);
        tap16(ws[k], v, acc);
    }
}

// ---------------- K4: e3 (GEMM K=128 over g_out2), relu ---------------------
__global__ __launch_bounds__(256, 2) void k_e3(const float* __restrict__ w,
                                               const float* __restrict__ bias) {
    const int c0 = blockIdx.y * 16;
    const int b  = (blockIdx.x * 256 + threadIdx.x) * 4;
    __shared__ float ws[128][16];
    for (int idx = threadIdx.x; idx < 128 * 16; idx += 256) {
        int k = idx >> 4, cc = idx & 15, ic = k >> 1, tp = k & 1;
        ws[k][cc] = w[((size_t)(c0 + cc) * 64 + ic) * 3 + 1 + tp];
    }
    u64 acc[8][4];
    init_bias(acc, bias, c0);
    __syncthreads();
    gemm_core<128>(ws, g_out2, b, acc);
#pragma unroll
    for (int m = 0; m < 8; m++) {
        int c = c0 + 2 * m;
        *reinterpret_cast<float4*>(&g_out3[(size_t)c * B_ + b])       = relu4(lo4(acc[m]));
        *reinterpret_cast<float4*>(&g_out3[(size_t)(c + 1) * B_ + b]) = relu4(hi4(acc[m]));
    }
}

// ---------------- K5: e4 (GEMM K=64 over g_out3, tap j=1), relu -------------
__global__ __launch_bounds__(256, 2) void k_e4(const float* __restrict__ w,
                                               const float* __restrict__ bias) {
    const int c0 = blockIdx.y * 16;
    const int b  = (blockIdx.x * 256 + threadIdx.x) * 4;
    __shared__ float ws[64][16];
    for (int idx = threadIdx.x; idx < 64 * 16; idx += 256) {
        int k = idx >> 4, cc = idx & 15;
        ws[k][cc] = w[((size_t)(c0 + cc) * 64 + k) * 3 + 1];
    }
    u64 acc[8][4];
    init_bias(acc, bias, c0);
    __syncthreads();
    gemm_core<64>(ws, g_out3, b, acc);
#pragma unroll
    for (int m = 0; m < 8; m++) {
        int c = c0 + 2 * m;
        *reinterpret_cast<float4*>(&g_out4[(size_t)c * B_ + b])       = relu4(lo4(acc[m]));
        *reinterpret_cast<float4*>(&g_out4[(size_t)(c + 1) * B_ + b]) = relu4(hi4(acc[m]));
    }
}

// ---------------- K6: LSTM gates (GEMM K=128 over g_out4) -------------------
__global__ __launch_bounds__(256, 2) void k_gates(const float* __restrict__ w_ih,
                                                  const float* __restrict__ b_ih,
                                                  const float* __restrict__ b_hh) {
    const int g0 = blockIdx.y * 16;
    const int b  = (blockIdx.x * 256 + threadIdx.x) * 4;
    __shared__ float ws[128][16];
    for (int idx = threadIdx.x; idx < 128 * 16; idx += 256) {
        int k = idx >> 4, cc = idx & 15;
        ws[k][cc] = w_ih[(size_t)(g0 + cc) * 128 + k];
    }
    u64 acc[8][4];
#pragma unroll
    for (int m = 0; m < 8; m++) {
        u64 bv = pack2(b_ih[g0 + 2 * m] + b_hh[g0 + 2 * m],
                       b_ih[g0 + 2 * m + 1] + b_hh[g0 + 2 * m + 1]);
#pragma unroll
        for (int p = 0; p < 4; p++) acc[m][p] = bv;
    }
    __syncthreads();
    gemm_core<128>(ws, g_out4, b, acc);
#pragma unroll
    for (int m = 0; m < 8; m++) {
        int g = g0 + 2 * m;
        *reinterpret_cast<float4*>(&g_gates[(size_t)g * B_ + b])       = lo4(acc[m]);
        *reinterpret_cast<float4*>(&g_gates[(size_t)(g + 1) * B_ + b]) = hi4(acc[m]);
    }
}

// ---------------- K7: LSTM pointwise (h0=c0=0) + decoder + sigmoid ----------
__device__ __forceinline__ float sigf(float x) { return 1.f / (1.f + expf(-x)); }

__global__ __launch_bounds__(256) void k_head(const float* __restrict__ dec_w,
                                              const float* __restrict__ dec_b,
                                              float* __restrict__ out) {
    const int b = (blockIdx.x * 256 + threadIdx.x) * 2;
    __shared__ float wd[128];
    if (threadIdx.x < 128) wd[threadIdx.x] = dec_w[threadIdx.x];
    __syncthreads();
    float d0 = dec_b[0], d1 = d0;
    for (int c = 0; c < 128; c++) {
        u64 ig = ld2(&g_gates[(size_t)(      c) * B_ + b]);
        u64 gg = ld2(&g_gates[(size_t)(256 + c) * B_ + b]);
        u64 og = ld2(&g_gates[(size_t)(384 + c) * B_ + b]);
        float wc = wd[c];
        float cA = sigf(lo32(ig)) * tanhf(lo32(gg));
        float hA = sigf(lo32(og)) * tanhf(cA);
        d0 += fmaxf(hA, 0.f) * wc;
        float cB = sigf(hi32(ig)) * tanhf(hi32(gg));
        float hB = sigf(hi32(og)) * tanhf(cB);
        d1 += fmaxf(hB, 0.f) * wc;
    }
    st2(&out[b], pack2(sigf(d0), sigf(d1)));
}

// ---------------- launch -----------------------------------------------------
extern "C" void kernel_launch(void* const* d_in, const int* in_sizes, int n_in,
                              void* d_out, int out_size) {
    const float* data   = (const float*)d_in[0];
    // d_in[1] = sr (16000 -> context 64, baked in)
    const float* stft_w = (const float*)d_in[2];
    const float* e1_w   = (const float*)d_in[3];
    const float* e1_b   = (const float*)d_in[4];
    const float* e2_w   = (const float*)d_in[5];
    const float* e2_b   = (const float*)d_in[6];
    const float* e3_w   = (const float*)d_in[7];
    const float* e3_b   = (const float*)d_in[8];
    const float* e4_w   = (const float*)d_in[9];
    const float* e4_b   = (const float*)d_in[10];
    const float* w_ih   = (const float*)d_in[11];
    // d_in[12] = w_hh (dead: h0 == 0)
    const float* b_ih   = (const float*)d_in[13];
    const float* b_hh   = (const float*)d_in[14];
    const float* dec_w  = (const float*)d_in[15];
    const float* dec_b  = (const float*)d_in[16];
    float* out = (float*)d_out;

    dim3 blk(256);
    const int GX = B_ / 1024;                 // 64 blocks over batch (4/thread)
    k_transpose<<<dim3(B_ / 32, 16), dim3(32, 8)>>>(data);
    k_stft     <<<dim3(GX, 17, 4), blk>>>(stft_w);   // 17*8 >= 129 freqs
    k_e1       <<<dim3(GX, 8, 4),  blk>>>(e1_w, e1_b);
    k_e2       <<<dim3(GX, 4, 2),  blk>>>(e2_w, e2_b);
    k_e3       <<<dim3(GX, 4),     blk>>>(e3_w, e3_b);
    k_e4       <<<dim3(GX, 8),     blk>>>(e4_w, e4_b);
    k_gates    <<<dim3(GX, 32),    blk>>>(w_ih, b_ih, b_hh);
    k_head     <<<dim3(B_ / 512),  blk>>>(dec_w, dec_b, out);
}